// round 1
// baseline (speedup 1.0000x reference)
#include <cuda_runtime.h>
#include <cstdint>

// ---------------------------------------------------------------------------
// MyRGCNConv: out[c] = (1/deg_c) * sum_{e in CSR row c} x[idx[e]] @ W[rel[e]]
//
// Phase 1: agg[c, r, :] = sum of x-rows of edges (c, rel=r)   [C, 8, 256]
// Phase 2: out = (agg.view(C, 2048) @ W.view(2048, 256)) / deg
// ---------------------------------------------------------------------------

#define D      256
#define NREL   8
#define KDIM   (NREL * D)     // 2048
#define MAXC   50000

// scratch: [C, NREL, D] fp32  (409.6 MB)
__device__ float g_agg[(size_t)MAXC * NREL * D];

// ---------------------------------------------------------------------------
// Phase 1: one block per center. 256 threads = one feature each.
// Edges are bucketed by relation in smem (tiny serial counting sort) so that
// each thread keeps acc[NREL] with *static* register indexing.
// ---------------------------------------------------------------------------
__global__ void __launch_bounds__(256) agg_kernel(
    const float* __restrict__ x,
    const int*   __restrict__ ptr,
    const int*   __restrict__ idx,
    const int*   __restrict__ rel)
{
    const int c = blockIdx.x;
    const int t = threadIdx.x;

    __shared__ int s_node[64];
    __shared__ int s_rel[64];
    __shared__ int s_perm[64];
    __shared__ int s_start[NREL + 1];

    const int beg = ptr[c];
    const int end = ptr[c + 1];

    float acc[NREL];
#pragma unroll
    for (int r = 0; r < NREL; ++r) acc[r] = 0.f;

    for (int base = beg; base < end; base += 64) {
        const int cnt = min(64, end - base);
        if (t < cnt) {
            s_node[t] = idx[base + t];
            s_rel[t]  = rel[base + t];
        }
        __syncthreads();
        if (t == 0) {               // counting sort of <=64 edges by relation
            int p = 0;
#pragma unroll
            for (int r = 0; r < NREL; ++r) {
                s_start[r] = p;
                for (int e = 0; e < cnt; ++e)
                    if (s_rel[e] == r) s_perm[p++] = s_node[e];
            }
            s_start[NREL] = p;
        }
        __syncthreads();
#pragma unroll
        for (int r = 0; r < NREL; ++r) {
            const int jb = s_start[r], je = s_start[r + 1];
            float a = acc[r];
            for (int j = jb; j < je; ++j)
                a += __ldg(&x[(size_t)s_perm[j] * D + t]);
            acc[r] = a;
        }
        __syncthreads();
    }

#pragma unroll
    for (int r = 0; r < NREL; ++r)
        g_agg[((size_t)c * NREL + r) * D + t] = acc[r];
}

// ---------------------------------------------------------------------------
// Phase 2: GEMM  C[M,256] = A[M,2048] * B[2048,256], then scale row c by
// 1/deg_c.  128x128x16 tile, 256 threads, 8x8 micro-tile per thread.
// Inner product uses packed fma.rn.f32x2 (2 FMA/issue -> 128 FMA/cyc/SM).
// ---------------------------------------------------------------------------
#define BM 128
#define BN 128
#define BK 16

__device__ __forceinline__ unsigned long long dup2(float a) {
    unsigned long long r;
    asm("mov.b64 %0, {%1, %1};" : "=l"(r) : "f"(a));
    return r;
}
__device__ __forceinline__ void fma2(unsigned long long& d,
                                     unsigned long long a,
                                     unsigned long long b) {
    asm("fma.rn.f32x2 %0, %1, %2, %0;" : "+l"(d) : "l"(a), "l"(b));
}
__device__ __forceinline__ void unpack2(unsigned long long v, float& lo, float& hi) {
    asm("mov.b64 {%0, %1}, %2;" : "=f"(lo), "=f"(hi) : "l"(v));
}

__global__ void __launch_bounds__(256, 2) gemm_kernel(
    const float* __restrict__ B,    // weights [2048, 256] row-major
    const int*   __restrict__ ptr,  // for deg
    float*       __restrict__ out,
    int M)
{
    const float* __restrict__ A = g_agg;

    __shared__ float As[BK][BM];    // transposed A tile: As[k][m]
    __shared__ float Bs[BK][BN];    // Bs[k][n]

    const int tid = threadIdx.x;
    const int bm  = blockIdx.x * BM;
    const int bn  = blockIdx.y * BN;

    const int tx = tid & 15;        // n group
    const int ty = tid >> 4;        // m group
    const int m0 = ty * 8;
    const int n0 = tx * 8;

    // global->smem load mappings (2 x float4 per thread for each of A, B)
    const int ar0 = tid >> 2;       // A row within tile (0..63, +64)
    const int ac4 = tid & 3;        // A float4-column (k/4)
    const int bkr = tid >> 5;       // B k-row (0..7, +8)
    const int bn4 = tid & 31;       // B float4-column (n/4)

    unsigned long long acc[8][4];
#pragma unroll
    for (int i = 0; i < 8; ++i)
#pragma unroll
        for (int j = 0; j < 4; ++j) acc[i][j] = 0ULL;

    const int KT = KDIM / BK;       // 128
    for (int kt = 0; kt < KT; ++kt) {
        const int bk = kt * BK;

        float4 av[2], bv[2];
#pragma unroll
        for (int i = 0; i < 2; ++i) {
            const int grow = bm + ar0 + i * 64;
            if (grow < M)
                av[i] = *(const float4*)&A[(size_t)grow * KDIM + bk + ac4 * 4];
            else
                av[i] = make_float4(0.f, 0.f, 0.f, 0.f);
            const int kr = bk + bkr + i * 8;
            bv[i] = *(const float4*)&B[(size_t)kr * 256 + bn + bn4 * 4];
        }

        __syncthreads();            // prior compute done before overwrite
#pragma unroll
        for (int i = 0; i < 2; ++i) {
            const int row = ar0 + i * 64;
            As[ac4 * 4 + 0][row] = av[i].x;
            As[ac4 * 4 + 1][row] = av[i].y;
            As[ac4 * 4 + 2][row] = av[i].z;
            As[ac4 * 4 + 3][row] = av[i].w;
            *(float4*)&Bs[bkr + i * 8][bn4 * 4] = bv[i];
        }
        __syncthreads();

#pragma unroll
        for (int kk = 0; kk < BK; ++kk) {
            const float4 a0 = *(const float4*)&As[kk][m0];
            const float4 a1 = *(const float4*)&As[kk][m0 + 4];
            const unsigned long long* pb =
                (const unsigned long long*)&Bs[kk][n0];
            unsigned long long bp[4];
            bp[0] = pb[0]; bp[1] = pb[1]; bp[2] = pb[2]; bp[3] = pb[3];

            unsigned long long ap[8];
            ap[0] = dup2(a0.x); ap[1] = dup2(a0.y);
            ap[2] = dup2(a0.z); ap[3] = dup2(a0.w);
            ap[4] = dup2(a1.x); ap[5] = dup2(a1.y);
            ap[6] = dup2(a1.z); ap[7] = dup2(a1.w);

#pragma unroll
            for (int i = 0; i < 8; ++i)
#pragma unroll
                for (int j = 0; j < 4; ++j)
                    fma2(acc[i][j], ap[i], bp[j]);
        }
    }

    // epilogue: divide by degree, store
#pragma unroll
    for (int i = 0; i < 8; ++i) {
        const int row = bm + m0 + i;
        if (row >= M) continue;
        const int deg = ptr[row + 1] - ptr[row];
        const float inv = 1.0f / (float)deg;
        float v[8];
#pragma unroll
        for (int j = 0; j < 4; ++j)
            unpack2(acc[i][j], v[2 * j], v[2 * j + 1]);
        float4 o0 = make_float4(v[0] * inv, v[1] * inv, v[2] * inv, v[3] * inv);
        float4 o1 = make_float4(v[4] * inv, v[5] * inv, v[6] * inv, v[7] * inv);
        float* dst = &out[(size_t)row * 256 + bn + n0];
        *(float4*)(dst)     = o0;
        *(float4*)(dst + 4) = o1;
    }
}

// ---------------------------------------------------------------------------
// inputs: 0=x[f32], 1=weights[f32], 2=ptr[i32], 3=idx[i32], 4=edge_types[i32],
//         5=num_node[i32]   ; output: f32 [C, 256]
// ---------------------------------------------------------------------------
extern "C" void kernel_launch(void* const* d_in, const int* in_sizes, int n_in,
                              void* d_out, int out_size) {
    const float* x   = (const float*)d_in[0];
    const float* w   = (const float*)d_in[1];
    const int*   ptr = (const int*)d_in[2];
    const int*   idx = (const int*)d_in[3];
    const int*   rel = (const int*)d_in[4];
    float*       out = (float*)d_out;

    const int C = in_sizes[2] - 1;          // number of centers

    agg_kernel<<<C, 256>>>(x, ptr, idx, rel);

    dim3 grid((C + BM - 1) / BM, 256 / BN);
    gemm_kernel<<<grid, 256>>>(w, ptr, out, C);
}

// round 3
// speedup vs baseline: 2.4971x; 2.4971x over previous
#include <cuda_runtime.h>
#include <cuda_bf16.h>
#include <cstdint>

// ===========================================================================
// MyRGCNConv via legacy tensor path (sm_100 base: mma.sync + ldmatrix + cp.async)
//  Phase 0: W[2048,256] f32 -> Bt_hi/Bt_lo bf16, transposed to [256 n][2048 k]
//  Phase 1: agg[c, r*256+d] per (center, relation); emitted as bf16 hi/lo
//  Phase 2: out = (Ah*Bh + Al*Bh + Ah*Bl) / deg  via m16n8k16 bf16 MMA
// ===========================================================================

#define DFEAT 256
#define NRELS 8
#define KDIM  2048
#define MAXM  50176

__device__ __align__(16) __nv_bfloat16 g_ahi[(size_t)MAXM * KDIM];
__device__ __align__(16) __nv_bfloat16 g_alo[(size_t)MAXM * KDIM];
__device__ __align__(16) __nv_bfloat16 g_bhi[(size_t)DFEAT * KDIM];  // [n][k]
__device__ __align__(16) __nv_bfloat16 g_blo[(size_t)DFEAT * KDIM];

// ---------------------------------------------------------------------------
__device__ __forceinline__ uint32_t smem_u32(const void* p) {
    uint32_t a;
    asm("{ .reg .u64 t; cvta.to.shared.u64 t, %1; cvt.u32.u64 %0, t; }"
        : "=r"(a) : "l"(p));
    return a;
}
__device__ __forceinline__ void cp16(uint32_t dst, const void* src) {
    asm volatile("cp.async.cg.shared.global [%0], [%1], 16;"
                 :: "r"(dst), "l"(src));
}
__device__ __forceinline__ void cp_commit() {
    asm volatile("cp.async.commit_group;");
}
__device__ __forceinline__ void ldm_x4(uint32_t& r0, uint32_t& r1,
                                       uint32_t& r2, uint32_t& r3, uint32_t a) {
    asm volatile("ldmatrix.sync.aligned.m8n8.x4.shared.b16 {%0,%1,%2,%3}, [%4];"
                 : "=r"(r0), "=r"(r1), "=r"(r2), "=r"(r3) : "r"(a));
}
__device__ __forceinline__ void mma_bf16(float* c, const uint32_t* a,
                                         uint32_t b0, uint32_t b1) {
    asm volatile(
        "mma.sync.aligned.m16n8k16.row.col.f32.bf16.bf16.f32 "
        "{%0,%1,%2,%3}, {%4,%5,%6,%7}, {%8,%9}, {%0,%1,%2,%3};"
        : "+f"(c[0]), "+f"(c[1]), "+f"(c[2]), "+f"(c[3])
        : "r"(a[0]), "r"(a[1]), "r"(a[2]), "r"(a[3]), "r"(b0), "r"(b1));
}

// ---------------------------------------------------------------------------
// Phase 0: weight transpose + bf16 split
// ---------------------------------------------------------------------------
__global__ void __launch_bounds__(256) wsplit_kernel(const float* __restrict__ w) {
    int i = blockIdx.x * 256 + threadIdx.x;   // over 256*2048
    int n = i >> 11;
    int k = i & 2047;
    float f = w[(size_t)k * DFEAT + n];
    __nv_bfloat16 h = __float2bfloat16(f);
    __nv_bfloat16 l = __float2bfloat16(f - __bfloat162float(h));
    g_bhi[i] = h;
    g_blo[i] = l;
}

// ---------------------------------------------------------------------------
// Phase 1: per-center aggregation -> bf16 hi/lo. 1 block = 1 center,
// 128 threads = 2 features each; no smem/syncs, predicated register accum.
// ---------------------------------------------------------------------------
__global__ void __launch_bounds__(128) agg_kernel(
    const float* __restrict__ x,
    const int*   __restrict__ ptr,
    const int*   __restrict__ idx,
    const int*   __restrict__ rel,
    int C)
{
    const int c = blockIdx.x;
    const int t = threadIdx.x;

    float a0[NRELS], a1[NRELS];
#pragma unroll
    for (int r = 0; r < NRELS; ++r) { a0[r] = 0.f; a1[r] = 0.f; }

    if (c < C) {
        const int beg = ptr[c];
        const int end = ptr[c + 1];
#pragma unroll 4
        for (int e = beg; e < end; ++e) {
            const int node = __ldg(idx + e);
            const int re   = __ldg(rel + e);
            const float2 v = __ldg((const float2*)(x + (size_t)node * DFEAT) + t);
#pragma unroll
            for (int r = 0; r < NRELS; ++r) {
                const bool m = (re == r);
                a0[r] += m ? v.x : 0.f;
                a1[r] += m ? v.y : 0.f;
            }
        }
    }

    const size_t base = (size_t)c * KDIM;
#pragma unroll
    for (int r = 0; r < NRELS; ++r) {
        const float f0 = a0[r], f1 = a1[r];
        __nv_bfloat16 h0 = __float2bfloat16(f0);
        __nv_bfloat16 h1 = __float2bfloat16(f1);
        __nv_bfloat16 l0 = __float2bfloat16(f0 - __bfloat162float(h0));
        __nv_bfloat16 l1 = __float2bfloat16(f1 - __bfloat162float(h1));
        __nv_bfloat162 hh; hh.x = h0; hh.y = h1;
        __nv_bfloat162 ll; ll.x = l0; ll.y = l1;
        ((__nv_bfloat162*)(g_ahi + base + r * DFEAT))[t] = hh;
        ((__nv_bfloat162*)(g_alo + base + r * DFEAT))[t] = ll;
    }
}

// ---------------------------------------------------------------------------
// Phase 2: GEMM  out[M,256] = A[M,2048] * Bt[256,2048]^T, / deg.
// CTA tile 128x128, BK=32, 8 warps of 64x32, double-buffered cp.async.
// Smem rows padded to 80B -> ldmatrix conflict-free.
// ---------------------------------------------------------------------------
#define BK     32
#define ROWB   80u                     // bytes per smem row (32 bf16 + 8 pad)
#define OFF_AH 0u
#define OFF_AL 10240u
#define OFF_BH 20480u
#define OFF_BL 30720u
#define STAGE  40960u
#define SMEMSZ (2u * STAGE)            // 81920 bytes

__global__ void __launch_bounds__(256, 2) gemm_kernel(
    const int* __restrict__ ptr,
    float*     __restrict__ out,
    int C)
{
    extern __shared__ char smem[];
    const uint32_t sbase = smem_u32(smem);
    const int tid  = threadIdx.x;
    const int lane = tid & 31;
    const int wid  = tid >> 5;
    const int bm   = blockIdx.x * 128;
    const int bn   = blockIdx.y * 128;

    const int warp_m = (wid & 1) * 64;
    const int warp_n = (wid >> 1) * 32;

    const __nv_bfloat16* __restrict__ Ah = g_ahi + (size_t)bm * KDIM;
    const __nv_bfloat16* __restrict__ Al = g_alo + (size_t)bm * KDIM;
    const __nv_bfloat16* __restrict__ Bh = g_bhi + (size_t)bn * KDIM;
    const __nv_bfloat16* __restrict__ Bl = g_blo + (size_t)bn * KDIM;

    // loader mapping: 512 16B chunks per matrix, 2 per thread per matrix
    const int ch0_row = tid >> 2;          // chunk tid      : rows 0..63
    const int ch1_row = (tid + 256) >> 2;  // chunk tid+256  : rows 64..127
    const int ch_c    = tid & 3;           // 16B column within row

    float acc[4][4][4];
#pragma unroll
    for (int i = 0; i < 4; ++i)
#pragma unroll
        for (int j = 0; j < 4; ++j)
#pragma unroll
            for (int q = 0; q < 4; ++q) acc[i][j][q] = 0.f;

#define LOAD_STAGE(kt, buf)                                                     \
    do {                                                                        \
        const int   k0_ = (kt) * BK;                                            \
        const uint32_t sb_ = sbase + (uint32_t)(buf) * STAGE;                   \
        const uint32_t d0_ = (uint32_t)ch0_row * ROWB + ch_c * 16;              \
        const uint32_t d1_ = (uint32_t)ch1_row * ROWB + ch_c * 16;              \
        const size_t  o0_ = (size_t)ch0_row * KDIM + k0_ + ch_c * 8;            \
        const size_t  o1_ = (size_t)ch1_row * KDIM + k0_ + ch_c * 8;            \
        cp16(sb_ + OFF_AH + d0_, Ah + o0_);                                     \
        cp16(sb_ + OFF_AH + d1_, Ah + o1_);                                     \
        cp16(sb_ + OFF_AL + d0_, Al + o0_);                                     \
        cp16(sb_ + OFF_AL + d1_, Al + o1_);                                     \
        cp16(sb_ + OFF_BH + d0_, Bh + o0_);                                     \
        cp16(sb_ + OFF_BH + d1_, Bh + o1_);                                     \
        cp16(sb_ + OFF_BL + d0_, Bl + o0_);                                     \
        cp16(sb_ + OFF_BL + d1_, Bl + o1_);                                     \
        cp_commit();                                                            \
    } while (0)

    // ldmatrix lane address components
    const uint32_t a_roff = (uint32_t)(warp_m + (lane & 15)) * ROWB +
                            (((uint32_t)lane >> 4) & 1) * 16;
    const uint32_t b_roff = (uint32_t)(warp_n + (((lane >> 4) & 1) * 8) + (lane & 7)) * ROWB +
                            (((uint32_t)lane >> 3) & 1) * 16;

    const int KT = KDIM / BK;      // 64
    LOAD_STAGE(0, 0);

    for (int kt = 0; kt < KT; ++kt) {
        const int buf = kt & 1;
        if (kt + 1 < KT) {
            LOAD_STAGE(kt + 1, buf ^ 1);
            asm volatile("cp.async.wait_group 1;");
        } else {
            asm volatile("cp.async.wait_group 0;");
        }
        __syncthreads();

        const uint32_t sb = sbase + (uint32_t)buf * STAGE;
#pragma unroll
        for (int kf = 0; kf < 2; ++kf) {
            const uint32_t kfo = (uint32_t)kf * 32;

            uint32_t ah[4][4], bhf[2][4], blf[2][4];
#pragma unroll
            for (int mf = 0; mf < 4; ++mf)
                ldm_x4(ah[mf][0], ah[mf][1], ah[mf][2], ah[mf][3],
                       sb + OFF_AH + a_roff + (uint32_t)mf * 16 * ROWB + kfo);
#pragma unroll
            for (int np = 0; np < 2; ++np) {
                ldm_x4(bhf[np][0], bhf[np][1], bhf[np][2], bhf[np][3],
                       sb + OFF_BH + b_roff + (uint32_t)np * 16 * ROWB + kfo);
                ldm_x4(blf[np][0], blf[np][1], blf[np][2], blf[np][3],
                       sb + OFF_BL + b_roff + (uint32_t)np * 16 * ROWB + kfo);
            }

#pragma unroll
            for (int mf = 0; mf < 4; ++mf)
#pragma unroll
                for (int nf = 0; nf < 4; ++nf) {
                    const uint32_t* bp = bhf[nf >> 1];
                    const uint32_t* lp = blf[nf >> 1];
                    const int s = (nf & 1) * 2;
                    mma_bf16(acc[mf][nf], ah[mf], bp[s], bp[s + 1]);
                    mma_bf16(acc[mf][nf], ah[mf], lp[s], lp[s + 1]);
                }

            uint32_t al[4][4];
#pragma unroll
            for (int mf = 0; mf < 4; ++mf)
                ldm_x4(al[mf][0], al[mf][1], al[mf][2], al[mf][3],
                       sb + OFF_AL + a_roff + (uint32_t)mf * 16 * ROWB + kfo);
#pragma unroll
            for (int mf = 0; mf < 4; ++mf)
#pragma unroll
                for (int nf = 0; nf < 4; ++nf) {
                    const uint32_t* bp = bhf[nf >> 1];
                    const int s = (nf & 1) * 2;
                    mma_bf16(acc[mf][nf], al[mf], bp[s], bp[s + 1]);
                }
        }
        __syncthreads();
    }

    // epilogue: /deg, store. acc frag: d0,d1 -> (row, col..col+1); d2,d3 -> row+8
#pragma unroll
    for (int mf = 0; mf < 4; ++mf) {
        const int r0 = bm + warp_m + mf * 16 + (lane >> 2);
        const int r1 = r0 + 8;
        float inv0 = 0.f, inv1 = 0.f;
        if (r0 < C) inv0 = 1.f / (float)(__ldg(ptr + r0 + 1) - __ldg(ptr + r0));
        if (r1 < C) inv1 = 1.f / (float)(__ldg(ptr + r1 + 1) - __ldg(ptr + r1));
#pragma unroll
        for (int nf = 0; nf < 4; ++nf) {
            const int col = bn + warp_n + nf * 8 + (lane & 3) * 2;
            if (r0 < C) {
                float2 o; o.x = acc[mf][nf][0] * inv0; o.y = acc[mf][nf][1] * inv0;
                *(float2*)(out + (size_t)r0 * DFEAT + col) = o;
            }
            if (r1 < C) {
                float2 o; o.x = acc[mf][nf][2] * inv1; o.y = acc[mf][nf][3] * inv1;
                *(float2*)(out + (size_t)r1 * DFEAT + col) = o;
            }
        }
    }
}

// ---------------------------------------------------------------------------
extern "C" void kernel_launch(void* const* d_in, const int* in_sizes, int n_in,
                              void* d_out, int out_size) {
    const float* x   = (const float*)d_in[0];
    const float* w   = (const float*)d_in[1];
    const int*   ptr = (const int*)d_in[2];
    const int*   idx = (const int*)d_in[3];
    const int*   rel = (const int*)d_in[4];
    float*       out = (float*)d_out;

    const int C    = in_sizes[2] - 1;
    const int nblk = (C + 127) / 128;

    cudaFuncSetAttribute(gemm_kernel,
                         cudaFuncAttributeMaxDynamicSharedMemorySize, SMEMSZ);

    wsplit_kernel<<<(DFEAT * KDIM) / 256, 256>>>(w);
    agg_kernel<<<nblk * 128, 128>>>(x, ptr, idx, rel, C);

    dim3 grid(nblk, DFEAT / 128);
    gemm_kernel<<<grid, 256, SMEMSZ>>>(ptr, out, C);
}